// round 14
// baseline (speedup 1.0000x reference)
#include <cuda_runtime.h>
#include <math.h>

// ---------------- problem constants ----------------
#define NB    2          // batch
#define LSEQ  4096       // H*W
#define DM    96         // d_model
#define DI    192        // d_inner
#define NS    16         // d_state
#define KDIR  4          // directions
#define KD    768        // K*D_INNER
#define KP    152        // K*(DT_RANK+2*D_STATE)
#define NCH   64         // number of chunks
#define CHS   64         // chunk size
#define MROWS (NB*LSEQ)  // 8192

// ---------------- device scratch ----------------
__device__ float  g_xx  [NB*LSEQ*DI];
__device__ float  g_z   [NB*LSEQ*DI];
__device__ float  g_xcr [NB*LSEQ*DI];
__device__ float  g_xct [NB*LSEQ*DI];
__device__ float  g_yn  [NB*LSEQ*DI];
__device__ float  g_bc  [NB*KDIR*LSEQ*32];
__device__ float  g_dts24[NB*LSEQ*24];
__device__ float  g_dtsp [NB*LSEQ*KD];
__device__ float2 g_agg  [NB*KDIR*NCH*DI*NS];
__device__ float  g_hst  [NB*KDIR*NCH*DI*NS];
__device__ float  g_ys   [NB*KDIR*LSEQ*DI];
__device__ float  g_WinT [96*384];
__device__ float  g_WxpT [768*152];
__device__ float  g_WdtT [24*768];
__device__ float  g_WoutT[192*96];
__device__ float  g_Ae   [KD*NS];
__device__ float  g_bsum [KD];

// ---------------- prep: transpose weights, A = -exp(A_log), bias fuse ----------------
__global__ void prep_kernel(const float* __restrict__ Win, const float* __restrict__ Wxp,
                            const float* __restrict__ Wdt, const float* __restrict__ Wout,
                            const float* __restrict__ Alog, const float* __restrict__ bdt,
                            const float* __restrict__ dtb) {
    const int n0 = 96*384, n1 = 768*152, n2 = 24*768, n3 = 192*96, n4 = 768*16, n5 = 768;
    const int total = n0+n1+n2+n3+n4+n5;
    for (int t = blockIdx.x*blockDim.x + threadIdx.x; t < total; t += gridDim.x*blockDim.x) {
        int e = t;
        if (e < n0) { int k = e/384, n = e%384; g_WinT[e] = Win[n*96 + k]; continue; }
        e -= n0;
        if (e < n1) { int k = e/152, p = e%152; g_WxpT[e] = Wxp[p*768 + k]; continue; }
        e -= n1;
        if (e < n2) { int r = e/768, n = e%768; g_WdtT[e] = Wdt[n*24 + r]; continue; }
        e -= n2;
        if (e < n3) { int d = e/96, j = e%96; g_WoutT[e] = Wout[j*192 + d]; continue; }
        e -= n3;
        if (e < n4) { g_Ae[e] = -expf(Alog[e]); continue; }
        e -= n4;
        g_bsum[e] = bdt[e] + dtb[e];
    }
}

// ---------------- K1: in-projection GEMM (8192x96 @ 96x384) + split/silu ----------------
__global__ void __launch_bounds__(256) k1_gemm(const float* __restrict__ X,
                                               const float* __restrict__ b_in) {
    __shared__ float As[64][17];
    __shared__ float Bs[16][64];
    const int tid = threadIdx.x;
    const int tx = tid & 15, ty = tid >> 4;
    const int m0 = blockIdx.x * 64, n0 = blockIdx.y * 64;
    const int lm = tid >> 2, lq = tid & 3;
    float acc[4][4] = {};
    for (int k0 = 0; k0 < 96; k0 += 16) {
        float4 av = *(const float4*)(X + (m0 + lm)*96 + k0 + lq*4);
        As[lm][lq*4+0] = av.x; As[lm][lq*4+1] = av.y;
        As[lm][lq*4+2] = av.z; As[lm][lq*4+3] = av.w;
        #pragma unroll
        for (int q = 0; q < 4; q++) {
            int e = tid + q*256;
            Bs[e>>6][e&63] = g_WinT[(k0 + (e>>6))*384 + n0 + (e&63)];
        }
        __syncthreads();
        #pragma unroll
        for (int kk = 0; kk < 16; kk++) {
            float ar[4], br[4];
            #pragma unroll
            for (int i = 0; i < 4; i++) ar[i] = As[ty + 16*i][kk];
            #pragma unroll
            for (int j = 0; j < 4; j++) br[j] = Bs[kk][tx + 16*j];
            #pragma unroll
            for (int i = 0; i < 4; i++)
                #pragma unroll
                for (int j = 0; j < 4; j++) acc[i][j] = fmaf(ar[i], br[j], acc[i][j]);
        }
        __syncthreads();
    }
    #pragma unroll
    for (int i = 0; i < 4; i++) {
        int m = m0 + ty + 16*i;
        #pragma unroll
        for (int j = 0; j < 4; j++) {
            int col = n0 + tx + 16*j;
            float v = acc[i][j] + b_in[col];
            if (col < 192) g_xx[m*192 + col] = v;
            else           g_z [m*192 + col - 192] = v / (1.f + __expf(-v));
        }
    }
}

// ---------------- K2: depthwise 3x3 conv + bias + silu; write rm & transposed ----------------
__global__ void __launch_bounds__(256) conv_dw(const float* __restrict__ cw,
                                               const float* __restrict__ cb) {
    __shared__ float sw[192*9];
    __shared__ float sb[192];
    for (int e = threadIdx.x; e < 1728; e += 256) sw[e] = cw[e];
    for (int e = threadIdx.x; e < 192;  e += 256) sb[e] = cb[e];
    __syncthreads();
    const int b = blockIdx.x >> 6, h = blockIdx.x & 63;
    for (int e = threadIdx.x; e < 64*192; e += 256) {
        int w = e / 192, c = e % 192;
        float acc = sb[c];
        #pragma unroll
        for (int kh = 0; kh < 3; kh++) {
            int hh = h + kh - 1;
            if ((unsigned)hh >= 64u) continue;
            #pragma unroll
            for (int kw = 0; kw < 3; kw++) {
                int ww = w + kw - 1;
                if ((unsigned)ww >= 64u) continue;
                acc = fmaf(g_xx[((b*64 + hh)*64 + ww)*192 + c], sw[c*9 + kh*3 + kw], acc);
            }
        }
        float sl = acc / (1.f + __expf(-acc));
        g_xcr[((b*64 + h)*64 + w)*192 + c] = sl;  // pixel order l = h*64+w
        g_xct[((b*64 + w)*64 + h)*192 + c] = sl;  // transposed order
    }
}

// ---------------- K3: x_dbl GEMM (8192 x 152, K=768) with direction gather ----------------
__global__ void __launch_bounds__(256) k3_gemm(const float* __restrict__ b_xp) {
    __shared__ float As[64][17];
    __shared__ float Bs[16][64];
    const int tid = threadIdx.x;
    const int tx = tid & 15, ty = tid >> 4;
    const int m0 = blockIdx.x * 64, n0 = blockIdx.y * 64;
    const int lm = tid >> 2, lq = tid & 3;
    const int gm = m0 + lm, bb = gm >> 12, l = gm & 4095;
    float acc[4][4] = {};
    for (int k0 = 0; k0 < 768; k0 += 16) {
        int seg = k0 / 192;                      // 192 % 16 == 0, tile stays inside a segment
        const float* src = (seg & 1) ? g_xct : g_xcr;
        int row = (seg & 2) ? (4095 - l) : l;
        float4 av = *(const float4*)(src + (bb*4096 + row)*192 + (k0 - seg*192) + lq*4);
        As[lm][lq*4+0] = av.x; As[lm][lq*4+1] = av.y;
        As[lm][lq*4+2] = av.z; As[lm][lq*4+3] = av.w;
        #pragma unroll
        for (int q = 0; q < 4; q++) {
            int e = tid + q*256;
            int p = n0 + (e & 63);
            Bs[e>>6][e&63] = (p < 152) ? g_WxpT[(k0 + (e>>6))*152 + p] : 0.f;
        }
        __syncthreads();
        #pragma unroll
        for (int kk = 0; kk < 16; kk++) {
            float ar[4], br[4];
            #pragma unroll
            for (int i = 0; i < 4; i++) ar[i] = As[ty + 16*i][kk];
            #pragma unroll
            for (int j = 0; j < 4; j++) br[j] = Bs[kk][tx + 16*j];
            #pragma unroll
            for (int i = 0; i < 4; i++)
                #pragma unroll
                for (int j = 0; j < 4; j++) acc[i][j] = fmaf(ar[i], br[j], acc[i][j]);
        }
        __syncthreads();
    }
    #pragma unroll
    for (int i = 0; i < 4; i++) {
        int m = m0 + ty + 16*i, mb = m >> 12, ml = m & 4095;
        #pragma unroll
        for (int j = 0; j < 4; j++) {
            int p = n0 + tx + 16*j;
            if (p < 152) {
                float v = acc[i][j] + b_xp[p];
                int kd = p / 38, jj = p % 38;
                if (jj < 6) g_dts24[m*24 + kd*6 + jj] = v;
                else        g_bc[((mb*4 + kd)*4096 + ml)*32 + (jj - 6)] = v;
            }
        }
    }
}

// ---------------- K4: dt projection (24 -> 768) + softplus(+dt_bias) ----------------
__global__ void __launch_bounds__(256) dt_proj() {
    const int row = blockIdx.x;
    __shared__ float sin24[24];
    if (threadIdx.x < 24) sin24[threadIdx.x] = g_dts24[row*24 + threadIdx.x];
    __syncthreads();
    for (int o = threadIdx.x; o < 768; o += 256) {
        float acc = g_bsum[o];
        #pragma unroll
        for (int r = 0; r < 24; r++) acc = fmaf(sin24[r], g_WdtT[r*768 + o], acc);
        float sp = (acc > 0.f) ? (acc + log1pf(expf(-acc))) : log1pf(expf(acc));
        g_dtsp[row*768 + o] = sp;
    }
}

// ---------------- K5a: per-chunk scan aggregates ----------------
__global__ void __launch_bounds__(192) scan_pass1() {
    const int blk = blockIdx.x;
    const int c = blk & 63, k = (blk >> 6) & 3, b = blk >> 8;
    const int d = threadIdx.x;
    __shared__ float sBC[64][32];
    const float* bcbase = g_bc + ((b*4 + k)*4096 + c*64)*32;
    for (int e = d; e < 2048; e += 192) sBC[e>>5][e&31] = bcbase[e];
    __syncthreads();
    float Ae[16];
    const float* aep = g_Ae + (k*192 + d)*16;
    #pragma unroll
    for (int n = 0; n < 16; n++) Ae[n] = aep[n];
    float h[16], Ag[16];
    #pragma unroll
    for (int n = 0; n < 16; n++) { h[n] = 0.f; Ag[n] = 1.f; }
    const float* dtp  = g_dtsp + (b*4096 + c*64)*768 + k*192 + d;
    const float* ubuf = ((k & 1) ? g_xct : g_xcr) + b*4096*192 + d;
    for (int li = 0; li < 64; li++) {
        int l = c*64 + li;
        float dts = dtp[li*768];
        int pos = (k & 2) ? (4095 - l) : l;
        float du = dts * ubuf[pos*192];
        #pragma unroll
        for (int n = 0; n < 16; n++) {
            float a = __expf(dts * Ae[n]);
            Ag[n] *= a;
            h[n] = fmaf(a, h[n], du * sBC[li][n]);
        }
    }
    float2* outp = g_agg + (((b*4 + k)*64 + c)*192 + d)*16;
    #pragma unroll
    for (int n = 0; n < 16; n++) outp[n] = make_float2(Ag[n], h[n]);
}

// ---------------- K5b: scan across chunk aggregates ----------------
__global__ void scan_pass2() {
    int t = blockIdx.x*blockDim.x + threadIdx.x;
    if (t >= 8*3072) return;
    int bk = t / 3072, dn = t % 3072;
    const float2* ag = g_agg + bk*64*3072 + dn;
    float* hs = g_hst + bk*64*3072 + dn;
    float h = 0.f;
    #pragma unroll 8
    for (int c = 0; c < 64; c++) {
        hs[c*3072] = h;
        float2 ab = ag[c*3072];
        h = fmaf(ab.x, h, ab.y);
    }
}

// ---------------- K5c: replay chunks with correct start state, produce y ----------------
__global__ void __launch_bounds__(192) scan_pass3(const float* __restrict__ Dskip) {
    const int blk = blockIdx.x;
    const int c = blk & 63, k = (blk >> 6) & 3, b = blk >> 8;
    const int d = threadIdx.x;
    __shared__ float sBC[64][32];
    const float* bcbase = g_bc + ((b*4 + k)*4096 + c*64)*32;
    for (int e = d; e < 2048; e += 192) sBC[e>>5][e&31] = bcbase[e];
    __syncthreads();
    float Ae[16];
    const float* aep = g_Ae + (k*192 + d)*16;
    #pragma unroll
    for (int n = 0; n < 16; n++) Ae[n] = aep[n];
    float h[16];
    const float* hs = g_hst + ((b*4 + k)*64 + c)*3072 + d*16;
    #pragma unroll
    for (int n = 0; n < 16; n++) h[n] = hs[n];
    const float Dk = Dskip[k*192 + d];
    const float* dtp  = g_dtsp + (b*4096 + c*64)*768 + k*192 + d;
    const float* ubuf = ((k & 1) ? g_xct : g_xcr) + b*4096*192 + d;
    float* yout = g_ys + ((b*4 + k)*4096 + c*64)*192 + d;
    for (int li = 0; li < 64; li++) {
        int l = c*64 + li;
        float dts = dtp[li*768];
        int pos = (k & 2) ? (4095 - l) : l;
        float u = ubuf[pos*192];
        float du = dts * u;
        float y = 0.f;
        #pragma unroll
        for (int n = 0; n < 16; n++) {
            float a = __expf(dts * Ae[n]);
            h[n] = fmaf(a, h[n], du * sBC[li][n]);
            y = fmaf(h[n], sBC[li][16 + n], y);
        }
        yout[li*192] = fmaf(u, Dk, y);
    }
}

// ---------------- K6: cross-merge + LayerNorm + z-gate (one warp per pixel) ----------------
__global__ void __launch_bounds__(256) merge_ln(const float* __restrict__ gamma,
                                                const float* __restrict__ beta) {
    const int warp = threadIdx.x >> 5, lane = threadIdx.x & 31;
    const int pix = blockIdx.x*8 + warp;
    const int b = pix >> 12, pl = pix & 4095;
    const int l1 = ((pl & 63) << 6) | (pl >> 6);
    const int l2 = 4095 - pl;
    const int l3 = 4095 - l1;
    const float* y0 = g_ys + ((b*4 + 0)*4096 + pl)*192;
    const float* y1 = g_ys + ((b*4 + 1)*4096 + l1)*192;
    const float* y2 = g_ys + ((b*4 + 2)*4096 + l2)*192;
    const float* y3 = g_ys + ((b*4 + 3)*4096 + l3)*192;
    float y[6]; float s = 0.f;
    #pragma unroll
    for (int i = 0; i < 6; i++) {
        int dd = lane + 32*i;
        y[i] = y0[dd] + y1[dd] + y2[dd] + y3[dd];
        s += y[i];
    }
    #pragma unroll
    for (int o = 16; o; o >>= 1) s += __shfl_xor_sync(0xffffffffu, s, o);
    float mu = s * (1.f/192.f);
    float v = 0.f;
    #pragma unroll
    for (int i = 0; i < 6; i++) { float t = y[i] - mu; v = fmaf(t, t, v); }
    #pragma unroll
    for (int o = 16; o; o >>= 1) v += __shfl_xor_sync(0xffffffffu, v, o);
    float rstd = rsqrtf(v * (1.f/192.f) + 1e-5f);
    const float* zr = g_z + (size_t)pix*192;
    float* yo = g_yn + (size_t)pix*192;
    #pragma unroll
    for (int i = 0; i < 6; i++) {
        int dd = lane + 32*i;
        float t = fmaf((y[i] - mu)*rstd, gamma[dd], beta[dd]);
        yo[dd] = t * zr[dd];
    }
}

// ---------------- K7: out projection (8192x192 @ 192x96) ----------------
__global__ void __launch_bounds__(256) k7_gemm(const float* __restrict__ b_out,
                                               float* __restrict__ out) {
    __shared__ float As[64][17];
    __shared__ float Bs[16][96];
    const int tid = threadIdx.x;
    const int tx = tid & 15, ty = tid >> 4;
    const int m0 = blockIdx.x * 64;
    const int lm = tid >> 2, lq = tid & 3;
    float acc[4][6] = {};
    for (int k0 = 0; k0 < 192; k0 += 16) {
        float4 av = *(const float4*)(g_yn + (m0 + lm)*192 + k0 + lq*4);
        As[lm][lq*4+0] = av.x; As[lm][lq*4+1] = av.y;
        As[lm][lq*4+2] = av.z; As[lm][lq*4+3] = av.w;
        #pragma unroll
        for (int q = 0; q < 6; q++) {
            int e = tid + q*256;
            Bs[e/96][e%96] = g_WoutT[(k0 + e/96)*96 + (e%96)];
        }
        __syncthreads();
        #pragma unroll
        for (int kk = 0; kk < 16; kk++) {
            float ar[4], br[6];
            #pragma unroll
            for (int i = 0; i < 4; i++) ar[i] = As[ty + 16*i][kk];
            #pragma unroll
            for (int j = 0; j < 6; j++) br[j] = Bs[kk][tx + 16*j];
            #pragma unroll
            for (int i = 0; i < 4; i++)
                #pragma unroll
                for (int j = 0; j < 6; j++) acc[i][j] = fmaf(ar[i], br[j], acc[i][j]);
        }
        __syncthreads();
    }
    #pragma unroll
    for (int i = 0; i < 4; i++) {
        int m = m0 + ty + 16*i;
        #pragma unroll
        for (int j = 0; j < 6; j++) {
            int col = tx + 16*j;
            out[m*96 + col] = acc[i][j] + b_out[col];
        }
    }
}

// ---------------- launch ----------------
extern "C" void kernel_launch(void* const* d_in, const int* in_sizes, int n_in,
                              void* d_out, int out_size) {
    const float* x       = (const float*)d_in[0];
    const float* W_in    = (const float*)d_in[1];
    const float* b_in    = (const float*)d_in[2];
    const float* conv_w  = (const float*)d_in[3];
    const float* conv_b  = (const float*)d_in[4];
    const float* W_xp    = (const float*)d_in[5];
    const float* b_xp    = (const float*)d_in[6];
    const float* W_dt    = (const float*)d_in[7];
    const float* b_dt    = (const float*)d_in[8];
    const float* A_log   = (const float*)d_in[9];
    const float* D_skip  = (const float*)d_in[10];
    const float* dt_bias = (const float*)d_in[11];
    const float* W_out   = (const float*)d_in[12];
    const float* b_out   = (const float*)d_in[13];
    const float* gamma   = (const float*)d_in[14];
    const float* beta    = (const float*)d_in[15];
    float* out = (float*)d_out;

    prep_kernel<<<256, 256>>>(W_in, W_xp, W_dt, W_out, A_log, b_dt, dt_bias);
    k1_gemm<<<dim3(MROWS/64, 6), 256>>>(x, b_in);
    conv_dw<<<NB*64, 256>>>(conv_w, conv_b);
    k3_gemm<<<dim3(MROWS/64, 3), 256>>>(b_xp);
    dt_proj<<<MROWS, 256>>>();
    scan_pass1<<<NB*KDIR*NCH, 192>>>();
    scan_pass2<<<96, 256>>>();
    scan_pass3<<<NB*KDIR*NCH, 192>>>(D_skip);
    merge_ln<<<MROWS/8, 256>>>(gamma, beta);
    k7_gemm<<<dim3(MROWS/64, 1), 256>>>(b_out, out);
}

// round 15
// speedup vs baseline: 1.1033x; 1.1033x over previous
#include <cuda_runtime.h>
#include <math.h>

// ---------------- problem constants ----------------
#define NB    2          // batch
#define LSEQ  4096       // H*W
#define DM    96         // d_model
#define DI    192        // d_inner
#define NS    16         // d_state
#define KDIR  4          // directions
#define KD    768        // K*D_INNER
#define KP    152        // K*(DT_RANK+2*D_STATE)
#define NCH   64         // number of chunks
#define CHS   64         // chunk size
#define MROWS (NB*LSEQ)  // 8192

// ---------------- device scratch ----------------
__device__ float  g_xx  [NB*LSEQ*DI];
__device__ float  g_z   [NB*LSEQ*DI];
__device__ float  g_xcr [NB*LSEQ*DI];
__device__ float  g_xct [NB*LSEQ*DI];
__device__ float  g_yn  [NB*LSEQ*DI];
__device__ float  g_bc  [NB*KDIR*LSEQ*32];
__device__ float  g_dts24[NB*LSEQ*24];
__device__ float  g_dtsp [NB*LSEQ*KD];
__device__ float2 g_agg  [NB*KDIR*NCH*DI*NS];
__device__ float  g_hst  [NB*KDIR*NCH*DI*NS];
__device__ float  g_ys   [NB*KDIR*LSEQ*DI];
__device__ float  g_WinT [96*384];
__device__ float  g_WxpT [768*152];
__device__ float  g_WdtT [24*768];
__device__ float  g_WoutT[192*96];
__device__ float  g_Ae   [KD*NS];
__device__ float  g_bsum [KD];

// ---------------- prep: transpose weights, A = -exp(A_log), bias fuse ----------------
__global__ void prep_kernel(const float* __restrict__ Win, const float* __restrict__ Wxp,
                            const float* __restrict__ Wdt, const float* __restrict__ Wout,
                            const float* __restrict__ Alog, const float* __restrict__ bdt,
                            const float* __restrict__ dtb) {
    const int n0 = 96*384, n1 = 768*152, n2 = 24*768, n3 = 192*96, n4 = 768*16, n5 = 768;
    const int total = n0+n1+n2+n3+n4+n5;
    for (int t = blockIdx.x*blockDim.x + threadIdx.x; t < total; t += gridDim.x*blockDim.x) {
        int e = t;
        if (e < n0) { int k = e/384, n = e%384; g_WinT[e] = Win[n*96 + k]; continue; }
        e -= n0;
        if (e < n1) { int k = e/152, p = e%152; g_WxpT[e] = Wxp[p*768 + k]; continue; }
        e -= n1;
        if (e < n2) { int r = e/768, n = e%768; g_WdtT[e] = Wdt[n*24 + r]; continue; }
        e -= n2;
        if (e < n3) { int d = e/96, j = e%96; g_WoutT[e] = Wout[j*192 + d]; continue; }
        e -= n3;
        if (e < n4) { g_Ae[e] = -expf(Alog[e]); continue; }
        e -= n4;
        g_bsum[e] = bdt[e] + dtb[e];
    }
}

// ---------------- K1: in-projection GEMM (8192x96 @ 96x384) + split/silu ----------------
// 128 threads, 64x64 tile, 8x4 register tile, vectorized smem reads.
__global__ void __launch_bounds__(128) k1_gemm(const float* __restrict__ X,
                                               const float* __restrict__ b_in) {
    __shared__ float As[16][68];   // k-major
    __shared__ float Bs[16][64];
    const int tid = threadIdx.x;
    const int tx = tid & 15;        // 4 cols each
    const int ty = tid >> 4;        // 8 rows each
    const int m0 = blockIdx.x * 64, n0 = blockIdx.y * 64;
    const int lm = tid >> 2, lq = tid & 3;    // lm 0..31
    float acc[8][4] = {};
    for (int k0 = 0; k0 < 96; k0 += 16) {
        float4 a0 = *(const float4*)(X + (m0 + lm)*96 + k0 + lq*4);
        float4 a1 = *(const float4*)(X + (m0 + lm + 32)*96 + k0 + lq*4);
        As[lq*4+0][lm] = a0.x; As[lq*4+1][lm] = a0.y;
        As[lq*4+2][lm] = a0.z; As[lq*4+3][lm] = a0.w;
        As[lq*4+0][lm+32] = a1.x; As[lq*4+1][lm+32] = a1.y;
        As[lq*4+2][lm+32] = a1.z; As[lq*4+3][lm+32] = a1.w;
        #pragma unroll
        for (int q = 0; q < 8; q++) {
            int e = tid + q*128;
            Bs[e>>6][e&63] = g_WinT[(k0 + (e>>6))*384 + n0 + (e&63)];
        }
        __syncthreads();
        #pragma unroll
        for (int kk = 0; kk < 16; kk++) {
            float4 av0 = *(const float4*)&As[kk][ty*8];
            float4 av1 = *(const float4*)&As[kk][ty*8+4];
            float4 bv  = *(const float4*)&Bs[kk][tx*4];
            float ar[8] = {av0.x,av0.y,av0.z,av0.w,av1.x,av1.y,av1.z,av1.w};
            float br[4] = {bv.x,bv.y,bv.z,bv.w};
            #pragma unroll
            for (int i = 0; i < 8; i++)
                #pragma unroll
                for (int j = 0; j < 4; j++) acc[i][j] = fmaf(ar[i], br[j], acc[i][j]);
        }
        __syncthreads();
    }
    #pragma unroll
    for (int i = 0; i < 8; i++) {
        int m = m0 + ty*8 + i;
        #pragma unroll
        for (int j = 0; j < 4; j++) {
            int col = n0 + tx*4 + j;
            float v = acc[i][j] + b_in[col];
            if (col < 192) g_xx[m*192 + col] = v;
            else           g_z [m*192 + col - 192] = v / (1.f + __expf(-v));
        }
    }
}

// ---------------- K2: depthwise 3x3 conv + bias + silu; write rm & transposed ----------------
__global__ void __launch_bounds__(256) conv_dw(const float* __restrict__ cw,
                                               const float* __restrict__ cb) {
    __shared__ float sw[192*9];
    __shared__ float sb[192];
    for (int e = threadIdx.x; e < 1728; e += 256) sw[e] = cw[e];
    for (int e = threadIdx.x; e < 192;  e += 256) sb[e] = cb[e];
    __syncthreads();
    const int b = blockIdx.x >> 6, h = blockIdx.x & 63;
    for (int e = threadIdx.x; e < 64*192; e += 256) {
        int w = e / 192, c = e % 192;
        float acc = sb[c];
        #pragma unroll
        for (int kh = 0; kh < 3; kh++) {
            int hh = h + kh - 1;
            if ((unsigned)hh >= 64u) continue;
            #pragma unroll
            for (int kw = 0; kw < 3; kw++) {
                int ww = w + kw - 1;
                if ((unsigned)ww >= 64u) continue;
                acc = fmaf(g_xx[((b*64 + hh)*64 + ww)*192 + c], sw[c*9 + kh*3 + kw], acc);
            }
        }
        float sl = acc / (1.f + __expf(-acc));
        g_xcr[((b*64 + h)*64 + w)*192 + c] = sl;  // pixel order l = h*64+w
        g_xct[((b*64 + w)*64 + h)*192 + c] = sl;  // transposed order
    }
}

// ---------------- K3: x_dbl GEMM (8192 x 152, K=768) with direction gather ----------------
// 128 threads, 64x64 tile, 8x4 register tile, vectorized smem reads.
__global__ void __launch_bounds__(128) k3_gemm(const float* __restrict__ b_xp) {
    __shared__ float As[16][68];   // k-major
    __shared__ float Bs[16][64];
    const int tid = threadIdx.x;
    const int tx = tid & 15;
    const int ty = tid >> 4;
    const int m0 = blockIdx.x * 64, n0 = blockIdx.y * 64;
    const int lm = tid >> 2, lq = tid & 3;
    const int gm0 = m0 + lm,      bb0 = gm0 >> 12, l0 = gm0 & 4095;
    const int gm1 = m0 + lm + 32, bb1 = gm1 >> 12, l1 = gm1 & 4095;
    float acc[8][4] = {};
    for (int k0 = 0; k0 < 768; k0 += 16) {
        int seg = k0 / 192;                      // tile stays inside a segment
        const float* src = (seg & 1) ? g_xct : g_xcr;
        int kc = k0 - seg*192 + lq*4;
        int r0 = (seg & 2) ? (4095 - l0) : l0;
        int r1 = (seg & 2) ? (4095 - l1) : l1;
        float4 a0 = *(const float4*)(src + (bb0*4096 + r0)*192 + kc);
        float4 a1 = *(const float4*)(src + (bb1*4096 + r1)*192 + kc);
        As[lq*4+0][lm] = a0.x; As[lq*4+1][lm] = a0.y;
        As[lq*4+2][lm] = a0.z; As[lq*4+3][lm] = a0.w;
        As[lq*4+0][lm+32] = a1.x; As[lq*4+1][lm+32] = a1.y;
        As[lq*4+2][lm+32] = a1.z; As[lq*4+3][lm+32] = a1.w;
        #pragma unroll
        for (int q = 0; q < 8; q++) {
            int e = tid + q*128;
            int p = n0 + (e & 63);
            Bs[e>>6][e&63] = (p < 152) ? g_WxpT[(k0 + (e>>6))*152 + p] : 0.f;
        }
        __syncthreads();
        #pragma unroll
        for (int kk = 0; kk < 16; kk++) {
            float4 av0 = *(const float4*)&As[kk][ty*8];
            float4 av1 = *(const float4*)&As[kk][ty*8+4];
            float4 bv  = *(const float4*)&Bs[kk][tx*4];
            float ar[8] = {av0.x,av0.y,av0.z,av0.w,av1.x,av1.y,av1.z,av1.w};
            float br[4] = {bv.x,bv.y,bv.z,bv.w};
            #pragma unroll
            for (int i = 0; i < 8; i++)
                #pragma unroll
                for (int j = 0; j < 4; j++) acc[i][j] = fmaf(ar[i], br[j], acc[i][j]);
        }
        __syncthreads();
    }
    #pragma unroll
    for (int i = 0; i < 8; i++) {
        int m = m0 + ty*8 + i, mb = m >> 12, ml = m & 4095;
        #pragma unroll
        for (int j = 0; j < 4; j++) {
            int p = n0 + tx*4 + j;
            if (p < 152) {
                float v = acc[i][j] + b_xp[p];
                int kd = p / 38, jj = p % 38;
                if (jj < 6) g_dts24[m*24 + kd*6 + jj] = v;
                else        g_bc[((mb*4 + kd)*4096 + ml)*32 + (jj - 6)] = v;
            }
        }
    }
}

// ---------------- K4: dt projection (24 -> 768) + softplus(+dt_bias) ----------------
// Each thread owns 3 outputs; W_dt column slice held in registers (loaded once).
// Block processes 64 rows with inputs staged in smem (broadcast reads).
__global__ void __launch_bounds__(256) dt_proj() {
    const int o0 = threadIdx.x * 3;
    float wr[24][3];
    #pragma unroll
    for (int r = 0; r < 24; r++) {
        wr[r][0] = g_WdtT[r*768 + o0];
        wr[r][1] = g_WdtT[r*768 + o0 + 1];
        wr[r][2] = g_WdtT[r*768 + o0 + 2];
    }
    const float b0 = g_bsum[o0], b1 = g_bsum[o0+1], b2 = g_bsum[o0+2];
    __shared__ float sin[64*24];
    const int row0 = blockIdx.x * 64;
    for (int e = threadIdx.x; e < 64*24; e += 256)
        sin[e] = g_dts24[row0*24 + e];
    __syncthreads();
    for (int rr = 0; rr < 64; rr++) {
        const float* s = sin + rr*24;
        float a0 = b0, a1 = b1, a2 = b2;
        #pragma unroll
        for (int r = 0; r < 24; r++) {
            float sv = s[r];
            a0 = fmaf(sv, wr[r][0], a0);
            a1 = fmaf(sv, wr[r][1], a1);
            a2 = fmaf(sv, wr[r][2], a2);
        }
        float* o = g_dtsp + (size_t)(row0 + rr)*768 + o0;
        o[0] = fmaxf(a0, 0.f) + log1pf(__expf(-fabsf(a0)));
        o[1] = fmaxf(a1, 0.f) + log1pf(__expf(-fabsf(a1)));
        o[2] = fmaxf(a2, 0.f) + log1pf(__expf(-fabsf(a2)));
    }
}

// ---------------- K5a: per-chunk scan aggregates ----------------
__global__ void __launch_bounds__(192) scan_pass1() {
    const int blk = blockIdx.x;
    const int c = blk & 63, k = (blk >> 6) & 3, b = blk >> 8;
    const int d = threadIdx.x;
    __shared__ float sBC[64][32];
    const float* bcbase = g_bc + ((b*4 + k)*4096 + c*64)*32;
    for (int e = d; e < 2048; e += 192) sBC[e>>5][e&31] = bcbase[e];
    __syncthreads();
    float Ae[16];
    const float* aep = g_Ae + (k*192 + d)*16;
    #pragma unroll
    for (int n = 0; n < 16; n++) Ae[n] = aep[n];
    float h[16], Ag[16];
    #pragma unroll
    for (int n = 0; n < 16; n++) { h[n] = 0.f; Ag[n] = 1.f; }
    const float* dtp  = g_dtsp + (b*4096 + c*64)*768 + k*192 + d;
    const float* ubuf = ((k & 1) ? g_xct : g_xcr) + b*4096*192 + d;
    for (int li = 0; li < 64; li++) {
        int l = c*64 + li;
        float dts = dtp[li*768];
        int pos = (k & 2) ? (4095 - l) : l;
        float du = dts * ubuf[pos*192];
        #pragma unroll
        for (int n = 0; n < 16; n++) {
            float a = __expf(dts * Ae[n]);
            Ag[n] *= a;
            h[n] = fmaf(a, h[n], du * sBC[li][n]);
        }
    }
    float2* outp = g_agg + (((b*4 + k)*64 + c)*192 + d)*16;
    #pragma unroll
    for (int n = 0; n < 16; n++) outp[n] = make_float2(Ag[n], h[n]);
}

// ---------------- K5b: scan across chunk aggregates ----------------
__global__ void scan_pass2() {
    int t = blockIdx.x*blockDim.x + threadIdx.x;
    if (t >= 8*3072) return;
    int bk = t / 3072, dn = t % 3072;
    const float2* ag = g_agg + bk*64*3072 + dn;
    float* hs = g_hst + bk*64*3072 + dn;
    float h = 0.f;
    #pragma unroll 8
    for (int c = 0; c < 64; c++) {
        hs[c*3072] = h;
        float2 ab = ag[c*3072];
        h = fmaf(ab.x, h, ab.y);
    }
}

// ---------------- K5c: replay chunks with correct start state, produce y ----------------
__global__ void __launch_bounds__(192) scan_pass3(const float* __restrict__ Dskip) {
    const int blk = blockIdx.x;
    const int c = blk & 63, k = (blk >> 6) & 3, b = blk >> 8;
    const int d = threadIdx.x;
    __shared__ float sBC[64][32];
    const float* bcbase = g_bc + ((b*4 + k)*4096 + c*64)*32;
    for (int e = d; e < 2048; e += 192) sBC[e>>5][e&31] = bcbase[e];
    __syncthreads();
    float Ae[16];
    const float* aep = g_Ae + (k*192 + d)*16;
    #pragma unroll
    for (int n = 0; n < 16; n++) Ae[n] = aep[n];
    float h[16];
    const float* hs = g_hst + ((b*4 + k)*64 + c)*3072 + d*16;
    #pragma unroll
    for (int n = 0; n < 16; n++) h[n] = hs[n];
    const float Dk = Dskip[k*192 + d];
    const float* dtp  = g_dtsp + (b*4096 + c*64)*768 + k*192 + d;
    const float* ubuf = ((k & 1) ? g_xct : g_xcr) + b*4096*192 + d;
    float* yout = g_ys + ((b*4 + k)*4096 + c*64)*192 + d;
    for (int li = 0; li < 64; li++) {
        int l = c*64 + li;
        float dts = dtp[li*768];
        int pos = (k & 2) ? (4095 - l) : l;
        float u = ubuf[pos*192];
        float du = dts * u;
        float y = 0.f;
        #pragma unroll
        for (int n = 0; n < 16; n++) {
            float a = __expf(dts * Ae[n]);
            h[n] = fmaf(a, h[n], du * sBC[li][n]);
            y = fmaf(h[n], sBC[li][16 + n], y);
        }
        yout[li*192] = fmaf(u, Dk, y);
    }
}

// ---------------- K6: cross-merge + LayerNorm + z-gate (one warp per pixel) ----------------
__global__ void __launch_bounds__(256) merge_ln(const float* __restrict__ gamma,
                                                const float* __restrict__ beta) {
    const int warp = threadIdx.x >> 5, lane = threadIdx.x & 31;
    const int pix = blockIdx.x*8 + warp;
    const int b = pix >> 12, pl = pix & 4095;
    const int l1 = ((pl & 63) << 6) | (pl >> 6);
    const int l2 = 4095 - pl;
    const int l3 = 4095 - l1;
    const float* y0 = g_ys + ((b*4 + 0)*4096 + pl)*192;
    const float* y1 = g_ys + ((b*4 + 1)*4096 + l1)*192;
    const float* y2 = g_ys + ((b*4 + 2)*4096 + l2)*192;
    const float* y3 = g_ys + ((b*4 + 3)*4096 + l3)*192;
    float y[6]; float s = 0.f;
    #pragma unroll
    for (int i = 0; i < 6; i++) {
        int dd = lane + 32*i;
        y[i] = y0[dd] + y1[dd] + y2[dd] + y3[dd];
        s += y[i];
    }
    #pragma unroll
    for (int o = 16; o; o >>= 1) s += __shfl_xor_sync(0xffffffffu, s, o);
    float mu = s * (1.f/192.f);
    float v = 0.f;
    #pragma unroll
    for (int i = 0; i < 6; i++) { float t = y[i] - mu; v = fmaf(t, t, v); }
    #pragma unroll
    for (int o = 16; o; o >>= 1) v += __shfl_xor_sync(0xffffffffu, v, o);
    float rstd = rsqrtf(v * (1.f/192.f) + 1e-5f);
    const float* zr = g_z + (size_t)pix*192;
    float* yo = g_yn + (size_t)pix*192;
    #pragma unroll
    for (int i = 0; i < 6; i++) {
        int dd = lane + 32*i;
        float t = fmaf((y[i] - mu)*rstd, gamma[dd], beta[dd]);
        yo[dd] = t * zr[dd];
    }
}

// ---------------- K7: out projection (8192x192 @ 192x96) ----------------
__global__ void __launch_bounds__(256) k7_gemm(const float* __restrict__ b_out,
                                               float* __restrict__ out) {
    __shared__ float As[64][17];
    __shared__ float Bs[16][96];
    const int tid = threadIdx.x;
    const int tx = tid & 15, ty = tid >> 4;
    const int m0 = blockIdx.x * 64;
    const int lm = tid >> 2, lq = tid & 3;
    float acc[4][6] = {};
    for (int k0 = 0; k0 < 192; k0 += 16) {
        float4 av = *(const float4*)(g_yn + (m0 + lm)*192 + k0 + lq*4);
        As[lm][lq*4+0] = av.x; As[lm][lq*4+1] = av.y;
        As[lm][lq*4+2] = av.z; As[lm][lq*4+3] = av.w;
        #pragma unroll
        for (int q = 0; q < 6; q++) {
            int e = tid + q*256;
            Bs[e/96][e%96] = g_WoutT[(k0 + e/96)*96 + (e%96)];
        }
        __syncthreads();
        #pragma unroll
        for (int kk = 0; kk < 16; kk++) {
            float ar[4], br[6];
            #pragma unroll
            for (int i = 0; i < 4; i++) ar[i] = As[ty + 16*i][kk];
            #pragma unroll
            for (int j = 0; j < 6; j++) br[j] = Bs[kk][tx + 16*j];
            #pragma unroll
            for (int i = 0; i < 4; i++)
                #pragma unroll
                for (int j = 0; j < 6; j++) acc[i][j] = fmaf(ar[i], br[j], acc[i][j]);
        }
        __syncthreads();
    }
    #pragma unroll
    for (int i = 0; i < 4; i++) {
        int m = m0 + ty + 16*i;
        #pragma unroll
        for (int j = 0; j < 6; j++) {
            int col = tx + 16*j;
            out[m*96 + col] = acc[i][j] + b_out[col];
        }
    }
}

// ---------------- launch ----------------
extern "C" void kernel_launch(void* const* d_in, const int* in_sizes, int n_in,
                              void* d_out, int out_size) {
    const float* x       = (const float*)d_in[0];
    const float* W_in    = (const float*)d_in[1];
    const float* b_in    = (const float*)d_in[2];
    const float* conv_w  = (const float*)d_in[3];
    const float* conv_b  = (const float*)d_in[4];
    const float* W_xp    = (const float*)d_in[5];
    const float* b_xp    = (const float*)d_in[6];
    const float* W_dt    = (const float*)d_in[7];
    const float* b_dt    = (const float*)d_in[8];
    const float* A_log   = (const float*)d_in[9];
    const float* D_skip  = (const float*)d_in[10];
    const float* dt_bias = (const float*)d_in[11];
    const float* W_out   = (const float*)d_in[12];
    const float* b_out   = (const float*)d_in[13];
    const float* gamma   = (const float*)d_in[14];
    const float* beta    = (const float*)d_in[15];
    float* out = (float*)d_out;

    prep_kernel<<<256, 256>>>(W_in, W_xp, W_dt, W_out, A_log, b_dt, dt_bias);
    k1_gemm<<<dim3(MROWS/64, 6), 128>>>(x, b_in);
    conv_dw<<<NB*64, 256>>>(conv_w, conv_b);
    k3_gemm<<<dim3(MROWS/64, 3), 128>>>(b_xp);
    dt_proj<<<MROWS/64, 256>>>();
    scan_pass1<<<NB*KDIR*NCH, 192>>>();
    scan_pass2<<<96, 256>>>();
    scan_pass3<<<NB*KDIR*NCH, 192>>>(D_skip);
    merge_ln<<<MROWS/8, 256>>>(gamma, beta);
    k7_gemm<<<dim3(MROWS/64, 1), 256>>>(b_out, out);
}

// round 16
// speedup vs baseline: 1.1309x; 1.0250x over previous
#include <cuda_runtime.h>
#include <math.h>

// ---------------- problem constants ----------------
#define NB    2          // batch
#define LSEQ  4096       // H*W
#define DM    96         // d_model
#define DI    192        // d_inner
#define NS    16         // d_state
#define KDIR  4          // directions
#define KD    768        // K*D_INNER
#define KP    152        // K*(DT_RANK+2*D_STATE)
#define NCH   64         // number of chunks
#define CHS   64         // chunk size
#define MROWS (NB*LSEQ)  // 8192

// ---------------- device scratch ----------------
__device__ float  g_xx  [NB*LSEQ*DI];
__device__ float  g_z   [NB*LSEQ*DI];
__device__ float  g_xcr [NB*LSEQ*DI];
__device__ float  g_xct [NB*LSEQ*DI];
__device__ float  g_yn  [NB*LSEQ*DI];
__device__ float  g_bc  [NB*KDIR*LSEQ*32];
__device__ float  g_dts24[NB*LSEQ*24];
__device__ float  g_dtsp [NB*LSEQ*KD];
__device__ float  g_part [KDIR*MROWS*KP];   // split-K partials for x_dbl GEMM
__device__ float2 g_agg  [NB*KDIR*NCH*DI*NS];
__device__ float  g_hst  [NB*KDIR*NCH*DI*NS];
__device__ float  g_ys   [NB*KDIR*LSEQ*DI];
__device__ float  g_WinT [96*384];
__device__ float  g_WxpT [768*152];
__device__ float  g_WdtT [24*768];
__device__ float  g_WoutT[192*96];
__device__ float  g_Ae   [KD*NS];
__device__ float  g_bsum [KD];

// ---------------- prep: transpose weights, A = -exp(A_log), bias fuse ----------------
__global__ void prep_kernel(const float* __restrict__ Win, const float* __restrict__ Wxp,
                            const float* __restrict__ Wdt, const float* __restrict__ Wout,
                            const float* __restrict__ Alog, const float* __restrict__ bdt,
                            const float* __restrict__ dtb) {
    const int n0 = 96*384, n1 = 768*152, n2 = 24*768, n3 = 192*96, n4 = 768*16, n5 = 768;
    const int total = n0+n1+n2+n3+n4+n5;
    for (int t = blockIdx.x*blockDim.x + threadIdx.x; t < total; t += gridDim.x*blockDim.x) {
        int e = t;
        if (e < n0) { int k = e/384, n = e%384; g_WinT[e] = Win[n*96 + k]; continue; }
        e -= n0;
        if (e < n1) { int k = e/152, p = e%152; g_WxpT[e] = Wxp[p*768 + k]; continue; }
        e -= n1;
        if (e < n2) { int r = e/768, n = e%768; g_WdtT[e] = Wdt[n*24 + r]; continue; }
        e -= n2;
        if (e < n3) { int d = e/96, j = e%96; g_WoutT[e] = Wout[j*192 + d]; continue; }
        e -= n3;
        if (e < n4) { g_Ae[e] = -expf(Alog[e]); continue; }
        e -= n4;
        g_bsum[e] = bdt[e] + dtb[e];
    }
}

// ---------------- K1: in-projection GEMM (8192x96 @ 96x384) + split/silu ----------------
__global__ void __launch_bounds__(128) k1_gemm(const float* __restrict__ X,
                                               const float* __restrict__ b_in) {
    __shared__ float As[16][68];   // k-major
    __shared__ float Bs[16][64];
    const int tid = threadIdx.x;
    const int tx = tid & 15;
    const int ty = tid >> 4;
    const int m0 = blockIdx.x * 64, n0 = blockIdx.y * 64;
    const int lm = tid >> 2, lq = tid & 3;
    float acc[8][4] = {};
    for (int k0 = 0; k0 < 96; k0 += 16) {
        float4 a0 = *(const float4*)(X + (m0 + lm)*96 + k0 + lq*4);
        float4 a1 = *(const float4*)(X + (m0 + lm + 32)*96 + k0 + lq*4);
        As[lq*4+0][lm] = a0.x; As[lq*4+1][lm] = a0.y;
        As[lq*4+2][lm] = a0.z; As[lq*4+3][lm] = a0.w;
        As[lq*4+0][lm+32] = a1.x; As[lq*4+1][lm+32] = a1.y;
        As[lq*4+2][lm+32] = a1.z; As[lq*4+3][lm+32] = a1.w;
        #pragma unroll
        for (int q = 0; q < 8; q++) {
            int e = tid + q*128;
            Bs[e>>6][e&63] = g_WinT[(k0 + (e>>6))*384 + n0 + (e&63)];
        }
        __syncthreads();
        #pragma unroll
        for (int kk = 0; kk < 16; kk++) {
            float4 av0 = *(const float4*)&As[kk][ty*8];
            float4 av1 = *(const float4*)&As[kk][ty*8+4];
            float4 bv  = *(const float4*)&Bs[kk][tx*4];
            float ar[8] = {av0.x,av0.y,av0.z,av0.w,av1.x,av1.y,av1.z,av1.w};
            float br[4] = {bv.x,bv.y,bv.z,bv.w};
            #pragma unroll
            for (int i = 0; i < 8; i++)
                #pragma unroll
                for (int j = 0; j < 4; j++) acc[i][j] = fmaf(ar[i], br[j], acc[i][j]);
        }
        __syncthreads();
    }
    #pragma unroll
    for (int i = 0; i < 8; i++) {
        int m = m0 + ty*8 + i;
        #pragma unroll
        for (int j = 0; j < 4; j++) {
            int col = n0 + tx*4 + j;
            float v = acc[i][j] + b_in[col];
            if (col < 192) g_xx[m*192 + col] = v;
            else           g_z [m*192 + col - 192] = v / (1.f + __expf(-v));
        }
    }
}

// ---------------- K2: depthwise 3x3 conv + bias + silu; write rm & transposed ----------------
__global__ void __launch_bounds__(256) conv_dw(const float* __restrict__ cw,
                                               const float* __restrict__ cb) {
    __shared__ float sw[192*9];
    __shared__ float sb[192];
    for (int e = threadIdx.x; e < 1728; e += 256) sw[e] = cw[e];
    for (int e = threadIdx.x; e < 192;  e += 256) sb[e] = cb[e];
    __syncthreads();
    const int b = blockIdx.x >> 6, h = blockIdx.x & 63;
    for (int e = threadIdx.x; e < 64*192; e += 256) {
        int w = e / 192, c = e % 192;
        float acc = sb[c];
        #pragma unroll
        for (int kh = 0; kh < 3; kh++) {
            int hh = h + kh - 1;
            if ((unsigned)hh >= 64u) continue;
            #pragma unroll
            for (int kw = 0; kw < 3; kw++) {
                int ww = w + kw - 1;
                if ((unsigned)ww >= 64u) continue;
                acc = fmaf(g_xx[((b*64 + hh)*64 + ww)*192 + c], sw[c*9 + kh*3 + kw], acc);
            }
        }
        float sl = acc / (1.f + __expf(-acc));
        g_xcr[((b*64 + h)*64 + w)*192 + c] = sl;  // pixel order l = h*64+w
        g_xct[((b*64 + w)*64 + h)*192 + c] = sl;  // transposed order
    }
}

// ---------------- K3: x_dbl GEMM, split-K by direction ----------------
// grid (128, 3, 4): blockIdx.z = direction segment (K slice of 192).
// Each block writes a fp32 partial (no bias) to g_part[seg].
__global__ void __launch_bounds__(128) k3_gemm() {
    __shared__ float As[16][68];   // k-major
    __shared__ float Bs[16][64];
    const int tid = threadIdx.x;
    const int tx = tid & 15;
    const int ty = tid >> 4;
    const int m0 = blockIdx.x * 64, n0 = blockIdx.y * 64;
    const int seg = blockIdx.z;
    const int lm = tid >> 2, lq = tid & 3;
    const int gm0 = m0 + lm,      bb0 = gm0 >> 12, l0 = gm0 & 4095;
    const int gm1 = m0 + lm + 32, bb1 = gm1 >> 12, l1 = gm1 & 4095;
    const float* src = (seg & 1) ? g_xct : g_xcr;
    const int r0 = (seg & 2) ? (4095 - l0) : l0;
    const int r1 = (seg & 2) ? (4095 - l1) : l1;
    const float* a0p = src + (bb0*4096 + r0)*192 + lq*4;
    const float* a1p = src + (bb1*4096 + r1)*192 + lq*4;
    float acc[8][4] = {};
    for (int k0 = 0; k0 < 192; k0 += 16) {
        float4 a0 = *(const float4*)(a0p + k0);
        float4 a1 = *(const float4*)(a1p + k0);
        As[lq*4+0][lm] = a0.x; As[lq*4+1][lm] = a0.y;
        As[lq*4+2][lm] = a0.z; As[lq*4+3][lm] = a0.w;
        As[lq*4+0][lm+32] = a1.x; As[lq*4+1][lm+32] = a1.y;
        As[lq*4+2][lm+32] = a1.z; As[lq*4+3][lm+32] = a1.w;
        #pragma unroll
        for (int q = 0; q < 8; q++) {
            int e = tid + q*128;
            int p = n0 + (e & 63);
            Bs[e>>6][e&63] = (p < 152) ? g_WxpT[(seg*192 + k0 + (e>>6))*152 + p] : 0.f;
        }
        __syncthreads();
        #pragma unroll
        for (int kk = 0; kk < 16; kk++) {
            float4 av0 = *(const float4*)&As[kk][ty*8];
            float4 av1 = *(const float4*)&As[kk][ty*8+4];
            float4 bv  = *(const float4*)&Bs[kk][tx*4];
            float ar[8] = {av0.x,av0.y,av0.z,av0.w,av1.x,av1.y,av1.z,av1.w};
            float br[4] = {bv.x,bv.y,bv.z,bv.w};
            #pragma unroll
            for (int i = 0; i < 8; i++)
                #pragma unroll
                for (int j = 0; j < 4; j++) acc[i][j] = fmaf(ar[i], br[j], acc[i][j]);
        }
        __syncthreads();
    }
    float* pbase = g_part + (size_t)seg*MROWS*KP;
    #pragma unroll
    for (int i = 0; i < 8; i++) {
        int m = m0 + ty*8 + i;
        #pragma unroll
        for (int j = 0; j < 4; j++) {
            int p = n0 + tx*4 + j;
            if (p < 152) pbase[m*KP + p] = acc[i][j];
        }
    }
}

// ---------------- K3b: reduce 4 split-K partials + bias, scatter to dts24 / bc ----------------
__global__ void __launch_bounds__(256) k3_reduce(const float* __restrict__ b_xp) {
    int idx = blockIdx.x*256 + threadIdx.x;
    if (idx >= MROWS*KP) return;
    int m = idx / KP, p = idx - m*KP;
    float v = b_xp[p];
    v += g_part[idx];
    v += g_part[idx + MROWS*KP];
    v += g_part[idx + 2*MROWS*KP];
    v += g_part[idx + 3*MROWS*KP];
    int mb = m >> 12, ml = m & 4095;
    int kd = p / 38, jj = p - kd*38;
    if (jj < 6) g_dts24[m*24 + kd*6 + jj] = v;
    else        g_bc[((mb*4 + kd)*4096 + ml)*32 + (jj - 6)] = v;
}

// ---------------- K4: dt projection (24 -> 768) + softplus(+dt_bias) ----------------
__global__ void __launch_bounds__(256) dt_proj() {
    const int o0 = threadIdx.x * 3;
    float wr[24][3];
    #pragma unroll
    for (int r = 0; r < 24; r++) {
        wr[r][0] = g_WdtT[r*768 + o0];
        wr[r][1] = g_WdtT[r*768 + o0 + 1];
        wr[r][2] = g_WdtT[r*768 + o0 + 2];
    }
    const float b0 = g_bsum[o0], b1 = g_bsum[o0+1], b2 = g_bsum[o0+2];
    __shared__ float sin[64*24];
    const int row0 = blockIdx.x * 64;
    for (int e = threadIdx.x; e < 64*24; e += 256)
        sin[e] = g_dts24[row0*24 + e];
    __syncthreads();
    for (int rr = 0; rr < 64; rr++) {
        const float* s = sin + rr*24;
        float a0 = b0, a1 = b1, a2 = b2;
        #pragma unroll
        for (int r = 0; r < 24; r++) {
            float sv = s[r];
            a0 = fmaf(sv, wr[r][0], a0);
            a1 = fmaf(sv, wr[r][1], a1);
            a2 = fmaf(sv, wr[r][2], a2);
        }
        float* o = g_dtsp + (size_t)(row0 + rr)*768 + o0;
        o[0] = fmaxf(a0, 0.f) + log1pf(__expf(-fabsf(a0)));
        o[1] = fmaxf(a1, 0.f) + log1pf(__expf(-fabsf(a1)));
        o[2] = fmaxf(a2, 0.f) + log1pf(__expf(-fabsf(a2)));
    }
}

// ---------------- K5a: per-chunk scan aggregates ----------------
__global__ void __launch_bounds__(192) scan_pass1() {
    const int blk = blockIdx.x;
    const int c = blk & 63, k = (blk >> 6) & 3, b = blk >> 8;
    const int d = threadIdx.x;
    __shared__ float sBC[64][32];
    const float* bcbase = g_bc + ((b*4 + k)*4096 + c*64)*32;
    for (int e = d; e < 2048; e += 192) sBC[e>>5][e&31] = bcbase[e];
    __syncthreads();
    float Ae[16];
    const float* aep = g_Ae + (k*192 + d)*16;
    #pragma unroll
    for (int n = 0; n < 16; n++) Ae[n] = aep[n];
    float h[16], Ag[16];
    #pragma unroll
    for (int n = 0; n < 16; n++) { h[n] = 0.f; Ag[n] = 1.f; }
    const float* dtp  = g_dtsp + (b*4096 + c*64)*768 + k*192 + d;
    const float* ubuf = ((k & 1) ? g_xct : g_xcr) + b*4096*192 + d;
    for (int li = 0; li < 64; li++) {
        int l = c*64 + li;
        float dts = dtp[li*768];
        int pos = (k & 2) ? (4095 - l) : l;
        float du = dts * ubuf[pos*192];
        #pragma unroll
        for (int n = 0; n < 16; n++) {
            float a = __expf(dts * Ae[n]);
            Ag[n] *= a;
            h[n] = fmaf(a, h[n], du * sBC[li][n]);
        }
    }
    float2* outp = g_agg + (((b*4 + k)*64 + c)*192 + d)*16;
    #pragma unroll
    for (int n = 0; n < 16; n++) outp[n] = make_float2(Ag[n], h[n]);
}

// ---------------- K5b: scan across chunk aggregates ----------------
__global__ void scan_pass2() {
    int t = blockIdx.x*blockDim.x + threadIdx.x;
    if (t >= 8*3072) return;
    int bk = t / 3072, dn = t % 3072;
    const float2* ag = g_agg + bk*64*3072 + dn;
    float* hs = g_hst + bk*64*3072 + dn;
    float h = 0.f;
    #pragma unroll 8
    for (int c = 0; c < 64; c++) {
        hs[c*3072] = h;
        float2 ab = ag[c*3072];
        h = fmaf(ab.x, h, ab.y);
    }
}

// ---------------- K5c: replay chunks with correct start state, produce y ----------------
__global__ void __launch_bounds__(192) scan_pass3(const float* __restrict__ Dskip) {
    const int blk = blockIdx.x;
    const int c = blk & 63, k = (blk >> 6) & 3, b = blk >> 8;
    const int d = threadIdx.x;
    __shared__ float sBC[64][32];
    const float* bcbase = g_bc + ((b*4 + k)*4096 + c*64)*32;
    for (int e = d; e < 2048; e += 192) sBC[e>>5][e&31] = bcbase[e];
    __syncthreads();
    float Ae[16];
    const float* aep = g_Ae + (k*192 + d)*16;
    #pragma unroll
    for (int n = 0; n < 16; n++) Ae[n] = aep[n];
    float h[16];
    const float* hs = g_hst + ((b*4 + k)*64 + c)*3072 + d*16;
    #pragma unroll
    for (int n = 0; n < 16; n++) h[n] = hs[n];
    const float Dk = Dskip[k*192 + d];
    const float* dtp  = g_dtsp + (b*4096 + c*64)*768 + k*192 + d;
    const float* ubuf = ((k & 1) ? g_xct : g_xcr) + b*4096*192 + d;
    float* yout = g_ys + ((b*4 + k)*4096 + c*64)*192 + d;
    for (int li = 0; li < 64; li++) {
        int l = c*64 + li;
        float dts = dtp[li*768];
        int pos = (k & 2) ? (4095 - l) : l;
        float u = ubuf[pos*192];
        float du = dts * u;
        float y = 0.f;
        #pragma unroll
        for (int n = 0; n < 16; n++) {
            float a = __expf(dts * Ae[n]);
            h[n] = fmaf(a, h[n], du * sBC[li][n]);
            y = fmaf(h[n], sBC[li][16 + n], y);
        }
        yout[li*192] = fmaf(u, Dk, y);
    }
}

// ---------------- K6: cross-merge + LayerNorm + z-gate (one warp per pixel) ----------------
__global__ void __launch_bounds__(256) merge_ln(const float* __restrict__ gamma,
                                                const float* __restrict__ beta) {
    const int warp = threadIdx.x >> 5, lane = threadIdx.x & 31;
    const int pix = blockIdx.x*8 + warp;
    const int b = pix >> 12, pl = pix & 4095;
    const int l1 = ((pl & 63) << 6) | (pl >> 6);
    const int l2 = 4095 - pl;
    const int l3 = 4095 - l1;
    const float* y0 = g_ys + ((b*4 + 0)*4096 + pl)*192;
    const float* y1 = g_ys + ((b*4 + 1)*4096 + l1)*192;
    const float* y2 = g_ys + ((b*4 + 2)*4096 + l2)*192;
    const float* y3 = g_ys + ((b*4 + 3)*4096 + l3)*192;
    float y[6]; float s = 0.f;
    #pragma unroll
    for (int i = 0; i < 6; i++) {
        int dd = lane + 32*i;
        y[i] = y0[dd] + y1[dd] + y2[dd] + y3[dd];
        s += y[i];
    }
    #pragma unroll
    for (int o = 16; o; o >>= 1) s += __shfl_xor_sync(0xffffffffu, s, o);
    float mu = s * (1.f/192.f);
    float v = 0.f;
    #pragma unroll
    for (int i = 0; i < 6; i++) { float t = y[i] - mu; v = fmaf(t, t, v); }
    #pragma unroll
    for (int o = 16; o; o >>= 1) v += __shfl_xor_sync(0xffffffffu, v, o);
    float rstd = rsqrtf(v * (1.f/192.f) + 1e-5f);
    const float* zr = g_z + (size_t)pix*192;
    float* yo = g_yn + (size_t)pix*192;
    #pragma unroll
    for (int i = 0; i < 6; i++) {
        int dd = lane + 32*i;
        float t = fmaf((y[i] - mu)*rstd, gamma[dd], beta[dd]);
        yo[dd] = t * zr[dd];
    }
}

// ---------------- K7: out projection (8192x192 @ 192x96) ----------------
__global__ void __launch_bounds__(256) k7_gemm(const float* __restrict__ b_out,
                                               float* __restrict__ out) {
    __shared__ float As[64][17];
    __shared__ float Bs[16][96];
    const int tid = threadIdx.x;
    const int tx = tid & 15, ty = tid >> 4;
    const int m0 = blockIdx.x * 64;
    const int lm = tid >> 2, lq = tid & 3;
    float acc[4][6] = {};
    for (int k0 = 0; k0 < 192; k0 += 16) {
        float4 av = *(const float4*)(g_yn + (m0 + lm)*192 + k0 + lq*4);
        As[lm][lq*4+0] = av.x; As[lm][lq*4+1] = av.y;
        As[lm][lq*4+2] = av.z; As[lm][lq*4+3] = av.w;
        #pragma unroll
        for (int q = 0; q < 6; q++) {
            int e = tid + q*256;
            Bs[e/96][e%96] = g_WoutT[(k0 + e/96)*96 + (e%96)];
        }
        __syncthreads();
        #pragma unroll
        for (int kk = 0; kk < 16; kk++) {
            float ar[4], br[6];
            #pragma unroll
            for (int i = 0; i < 4; i++) ar[i] = As[ty + 16*i][kk];
            #pragma unroll
            for (int j = 0; j < 6; j++) br[j] = Bs[kk][tx + 16*j];
            #pragma unroll
            for (int i = 0; i < 4; i++)
                #pragma unroll
                for (int j = 0; j < 6; j++) acc[i][j] = fmaf(ar[i], br[j], acc[i][j]);
        }
        __syncthreads();
    }
    #pragma unroll
    for (int i = 0; i < 4; i++) {
        int m = m0 + ty + 16*i;
        #pragma unroll
        for (int j = 0; j < 6; j++) {
            int col = tx + 16*j;
            out[m*96 + col] = acc[i][j] + b_out[col];
        }
    }
}

// ---------------- launch ----------------
extern "C" void kernel_launch(void* const* d_in, const int* in_sizes, int n_in,
                              void* d_out, int out_size) {
    const float* x       = (const float*)d_in[0];
    const float* W_in    = (const float*)d_in[1];
    const float* b_in    = (const float*)d_in[2];
    const float* conv_w  = (const float*)d_in[3];
    const float* conv_b  = (const float*)d_in[4];
    const float* W_xp    = (const float*)d_in[5];
    const float* b_xp    = (const float*)d_in[6];
    const float* W_dt    = (const float*)d_in[7];
    const float* b_dt    = (const float*)d_in[8];
    const float* A_log   = (const float*)d_in[9];
    const float* D_skip  = (const float*)d_in[10];
    const float* dt_bias = (const float*)d_in[11];
    const float* W_out   = (const float*)d_in[12];
    const float* b_out   = (const float*)d_in[13];
    const float* gamma   = (const float*)d_in[14];
    const float* beta    = (const float*)d_in[15];
    float* out = (float*)d_out;

    prep_kernel<<<256, 256>>>(W_in, W_xp, W_dt, W_out, A_log, b_dt, dt_bias);
    k1_gemm<<<dim3(MROWS/64, 6), 128>>>(x, b_in);
    conv_dw<<<NB*64, 256>>>(conv_w, conv_b);
    k3_gemm<<<dim3(MROWS/64, 3, 4), 128>>>();
    k3_reduce<<<(MROWS*KP + 255)/256, 256>>>(b_xp);
    dt_proj<<<MROWS/64, 256>>>();
    scan_pass1<<<NB*KDIR*NCH, 192>>>();
    scan_pass2<<<96, 256>>>();
    scan_pass3<<<NB*KDIR*NCH, 192>>>(D_skip);
    merge_ln<<<MROWS/8, 256>>>(gamma, beta);
    k7_gemm<<<dim3(MROWS/64, 1), 256>>>(b_out, out);
}

// round 17
// speedup vs baseline: 1.2223x; 1.0808x over previous
#include <cuda_runtime.h>
#include <math.h>
#include <stdint.h>

// ---------------- problem constants ----------------
#define NB    2          // batch
#define LSEQ  4096       // H*W
#define DM    96         // d_model
#define DI    192        // d_inner
#define NS    16         // d_state
#define KDIR  4          // directions
#define KD    768        // K*D_INNER
#define KP    152        // K*(DT_RANK+2*D_STATE)
#define NCH   64         // number of chunks
#define CHS   64         // chunk size
#define MROWS (NB*LSEQ)  // 8192

// ---------------- device scratch ----------------
__device__ float  g_xx  [NB*LSEQ*DI];
__device__ float  g_z   [NB*LSEQ*DI];
__device__ float  g_xcr [NB*LSEQ*DI];
__device__ float  g_xct [NB*LSEQ*DI];
__device__ float  g_yn  [NB*LSEQ*DI];
__device__ float  g_bc  [NB*KDIR*LSEQ*32];
__device__ float  g_dts24[NB*LSEQ*24];
__device__ float  g_dtsp [NB*LSEQ*KD];
__device__ float  g_part [KDIR*MROWS*KP];   // split-K partials for x_dbl GEMM
__device__ float2 g_agg  [NB*KDIR*NCH*DI*NS];
__device__ float  g_hst  [NB*KDIR*NCH*DI*NS];
__device__ float  g_ys   [NB*KDIR*LSEQ*DI];
__device__ float  g_WinT [96*384];
__device__ float  g_WxpT [768*152];
__device__ float  g_WdtT [24*768];
__device__ float  g_WoutT[192*96];
__device__ float  g_Ae   [KD*NS];
__device__ float  g_bsum [KD];

// ---------------- helpers ----------------
__device__ __forceinline__ float cvt_tf32(float v) {
    uint32_t u;
    asm("cvt.rna.tf32.f32 %0, %1;" : "=r"(u) : "f"(v));
    return __uint_as_float(u);
}

// ---------------- prep: transpose weights, A = -exp(A_log), bias fuse ----------------
__global__ void prep_kernel(const float* __restrict__ Win, const float* __restrict__ Wxp,
                            const float* __restrict__ Wdt, const float* __restrict__ Wout,
                            const float* __restrict__ Alog, const float* __restrict__ bdt,
                            const float* __restrict__ dtb) {
    const int n0 = 96*384, n1 = 768*152, n2 = 24*768, n3 = 192*96, n4 = 768*16, n5 = 768;
    const int total = n0+n1+n2+n3+n4+n5;
    for (int t = blockIdx.x*blockDim.x + threadIdx.x; t < total; t += gridDim.x*blockDim.x) {
        int e = t;
        if (e < n0) { int k = e/384, n = e%384; g_WinT[e] = Win[n*96 + k]; continue; }
        e -= n0;
        if (e < n1) { int k = e/152, p = e%152; g_WxpT[e] = Wxp[p*768 + k]; continue; }
        e -= n1;
        if (e < n2) { int r = e/768, n = e%768; g_WdtT[e] = Wdt[n*24 + r]; continue; }
        e -= n2;
        if (e < n3) { int d = e/96, j = e%96; g_WoutT[e] = Wout[j*192 + d]; continue; }
        e -= n3;
        if (e < n4) { g_Ae[e] = -expf(Alog[e]); continue; }
        e -= n4;
        g_bsum[e] = bdt[e] + dtb[e];
    }
}

// ---------------- K1: in-projection GEMM (8192x96 @ 96x384) + split/silu ----------------
__global__ void __launch_bounds__(128) k1_gemm(const float* __restrict__ X,
                                               const float* __restrict__ b_in) {
    __shared__ float As[16][68];   // k-major
    __shared__ float Bs[16][64];
    const int tid = threadIdx.x;
    const int tx = tid & 15;
    const int ty = tid >> 4;
    const int m0 = blockIdx.x * 64, n0 = blockIdx.y * 64;
    const int lm = tid >> 2, lq = tid & 3;
    float acc[8][4] = {};
    for (int k0 = 0; k0 < 96; k0 += 16) {
        float4 a0 = *(const float4*)(X + (m0 + lm)*96 + k0 + lq*4);
        float4 a1 = *(const float4*)(X + (m0 + lm + 32)*96 + k0 + lq*4);
        As[lq*4+0][lm] = a0.x; As[lq*4+1][lm] = a0.y;
        As[lq*4+2][lm] = a0.z; As[lq*4+3][lm] = a0.w;
        As[lq*4+0][lm+32] = a1.x; As[lq*4+1][lm+32] = a1.y;
        As[lq*4+2][lm+32] = a1.z; As[lq*4+3][lm+32] = a1.w;
        #pragma unroll
        for (int q = 0; q < 8; q++) {
            int e = tid + q*128;
            Bs[e>>6][e&63] = g_WinT[(k0 + (e>>6))*384 + n0 + (e&63)];
        }
        __syncthreads();
        #pragma unroll
        for (int kk = 0; kk < 16; kk++) {
            float4 av0 = *(const float4*)&As[kk][ty*8];
            float4 av1 = *(const float4*)&As[kk][ty*8+4];
            float4 bv  = *(const float4*)&Bs[kk][tx*4];
            float ar[8] = {av0.x,av0.y,av0.z,av0.w,av1.x,av1.y,av1.z,av1.w};
            float br[4] = {bv.x,bv.y,bv.z,bv.w};
            #pragma unroll
            for (int i = 0; i < 8; i++)
                #pragma unroll
                for (int j = 0; j < 4; j++) acc[i][j] = fmaf(ar[i], br[j], acc[i][j]);
        }
        __syncthreads();
    }
    #pragma unroll
    for (int i = 0; i < 8; i++) {
        int m = m0 + ty*8 + i;
        #pragma unroll
        for (int j = 0; j < 4; j++) {
            int col = n0 + tx*4 + j;
            float v = acc[i][j] + b_in[col];
            if (col < 192) g_xx[m*192 + col] = v;
            else           g_z [m*192 + col - 192] = v / (1.f + __expf(-v));
        }
    }
}

// ---------------- K2: depthwise 3x3 conv + bias + silu; write rm & transposed ----------------
__global__ void __launch_bounds__(256) conv_dw(const float* __restrict__ cw,
                                               const float* __restrict__ cb) {
    __shared__ float sw[192*9];
    __shared__ float sb[192];
    for (int e = threadIdx.x; e < 1728; e += 256) sw[e] = cw[e];
    for (int e = threadIdx.x; e < 192;  e += 256) sb[e] = cb[e];
    __syncthreads();
    const int b = blockIdx.x >> 6, h = blockIdx.x & 63;
    for (int e = threadIdx.x; e < 64*192; e += 256) {
        int w = e / 192, c = e % 192;
        float acc = sb[c];
        #pragma unroll
        for (int kh = 0; kh < 3; kh++) {
            int hh = h + kh - 1;
            if ((unsigned)hh >= 64u) continue;
            #pragma unroll
            for (int kw = 0; kw < 3; kw++) {
                int ww = w + kw - 1;
                if ((unsigned)ww >= 64u) continue;
                acc = fmaf(g_xx[((b*64 + hh)*64 + ww)*192 + c], sw[c*9 + kh*3 + kw], acc);
            }
        }
        float sl = acc / (1.f + __expf(-acc));
        g_xcr[((b*64 + h)*64 + w)*192 + c] = sl;  // pixel order l = h*64+w
        g_xct[((b*64 + w)*64 + h)*192 + c] = sl;  // transposed order
    }
}

// ---------------- K3: x_dbl GEMM via tf32 mma.sync, split-K by direction ----------------
// grid (128, 3, 4): blockIdx.z = direction segment (K slice of 192).
// Block: 128 thr (4 warps), tile 64x64; each warp 32x32 = 2x4 m16n8k8 tiles.
// A/B staged in smem with stride-20 rows (conflict-free for the frag pattern),
// tf32-converted once at staging. fp32 accum; partials to g_part[seg].
__global__ void __launch_bounds__(128) k3_gemm() {
    __shared__ float As[64][20];   // m-major: As[m][k]
    __shared__ float Bs[64][20];   // n-major: Bs[n][k]
    const int tid  = threadIdx.x;
    const int warp = tid >> 5, lane = tid & 31;
    const int warpM = warp & 1, warpN = warp >> 1;
    const int m0 = blockIdx.x * 64, n0 = blockIdx.y * 64;
    const int seg = blockIdx.z;

    // A staging addresses (direction gather, loop-invariant)
    const int lm = tid >> 2, lq = tid & 3;
    const int gm0 = m0 + lm,      bb0 = gm0 >> 12, l0 = gm0 & 4095;
    const int gm1 = m0 + lm + 32, bb1 = gm1 >> 12, l1 = gm1 & 4095;
    const float* src = (seg & 1) ? g_xct : g_xcr;
    const int r0 = (seg & 2) ? (4095 - l0) : l0;
    const int r1 = (seg & 2) ? (4095 - l1) : l1;
    const float* a0p = src + (bb0*4096 + r0)*192 + lq*4;
    const float* a1p = src + (bb1*4096 + r1)*192 + lq*4;

    float c[2][4][4];
    #pragma unroll
    for (int mt = 0; mt < 2; mt++)
        #pragma unroll
        for (int nt = 0; nt < 4; nt++)
            #pragma unroll
            for (int i = 0; i < 4; i++) c[mt][nt][i] = 0.f;

    const int frow = lane >> 2;       // 0..7
    const int fk   = lane & 3;        // 0..3

    for (int k0 = 0; k0 < 192; k0 += 16) {
        // stage A (2 rows per thread, 4 cols, tf32-converted)
        float4 a0 = *(const float4*)(a0p + k0);
        float4 a1 = *(const float4*)(a1p + k0);
        float4 t0 = make_float4(cvt_tf32(a0.x), cvt_tf32(a0.y), cvt_tf32(a0.z), cvt_tf32(a0.w));
        float4 t1 = make_float4(cvt_tf32(a1.x), cvt_tf32(a1.y), cvt_tf32(a1.z), cvt_tf32(a1.w));
        *(float4*)&As[lm][lq*4]      = t0;
        *(float4*)&As[lm + 32][lq*4] = t1;
        // stage B: 16x64 panel, n-major
        #pragma unroll
        for (int q = 0; q < 8; q++) {
            int e = tid + q*128;
            int kk = e >> 6, nn = e & 63;
            int p = n0 + nn;
            float v = (p < 152) ? g_WxpT[(seg*192 + k0 + kk)*152 + p] : 0.f;
            Bs[nn][kk] = cvt_tf32(v);
        }
        __syncthreads();
        #pragma unroll
        for (int ks = 0; ks < 16; ks += 8) {
            uint32_t af[2][4], bf[4][2];
            const int ar = warpM*32 + frow;
            const int ac = ks + fk;
            #pragma unroll
            for (int mt = 0; mt < 2; mt++) {
                af[mt][0] = __float_as_uint(As[ar + mt*16    ][ac]);
                af[mt][1] = __float_as_uint(As[ar + mt*16 + 8][ac]);
                af[mt][2] = __float_as_uint(As[ar + mt*16    ][ac + 4]);
                af[mt][3] = __float_as_uint(As[ar + mt*16 + 8][ac + 4]);
            }
            const int bn = warpN*32 + frow;
            #pragma unroll
            for (int nt = 0; nt < 4; nt++) {
                bf[nt][0] = __float_as_uint(Bs[bn + nt*8][ac]);
                bf[nt][1] = __float_as_uint(Bs[bn + nt*8][ac + 4]);
            }
            #pragma unroll
            for (int mt = 0; mt < 2; mt++)
                #pragma unroll
                for (int nt = 0; nt < 4; nt++) {
                    asm volatile(
                        "mma.sync.aligned.m16n8k8.row.col.f32.tf32.tf32.f32 "
                        "{%0,%1,%2,%3},{%4,%5,%6,%7},{%8,%9},{%0,%1,%2,%3};"
                        : "+f"(c[mt][nt][0]), "+f"(c[mt][nt][1]),
                          "+f"(c[mt][nt][2]), "+f"(c[mt][nt][3])
                        : "r"(af[mt][0]), "r"(af[mt][1]), "r"(af[mt][2]), "r"(af[mt][3]),
                          "r"(bf[nt][0]), "r"(bf[nt][1]));
                }
        }
        __syncthreads();
    }
    // write partials
    float* pbase = g_part + (size_t)seg*MROWS*KP;
    const int row0 = m0 + warpM*32 + frow;
    const int col0 = n0 + warpN*32 + 2*fk;
    #pragma unroll
    for (int mt = 0; mt < 2; mt++) {
        #pragma unroll
        for (int nt = 0; nt < 4; nt++) {
            int p = col0 + nt*8;
            if (p < 152) {
                int ra = row0 + mt*16;
                *(float2*)&pbase[ra*KP + p]       = make_float2(c[mt][nt][0], c[mt][nt][1]);
                *(float2*)&pbase[(ra + 8)*KP + p] = make_float2(c[mt][nt][2], c[mt][nt][3]);
            }
        }
    }
}

// ---------------- K3b: reduce 4 split-K partials + bias, scatter to dts24 / bc ----------------
__global__ void __launch_bounds__(256) k3_reduce(const float* __restrict__ b_xp) {
    int idx = blockIdx.x*256 + threadIdx.x;
    if (idx >= MROWS*KP) return;
    int m = idx / KP, p = idx - m*KP;
    float v = b_xp[p];
    v += g_part[idx];
    v += g_part[idx + MROWS*KP];
    v += g_part[idx + 2*MROWS*KP];
    v += g_part[idx + 3*MROWS*KP];
    int mb = m >> 12, ml = m & 4095;
    int kd = p / 38, jj = p - kd*38;
    if (jj < 6) g_dts24[m*24 + kd*6 + jj] = v;
    else        g_bc[((mb*4 + kd)*4096 + ml)*32 + (jj - 6)] = v;
}

// ---------------- K4: dt projection (24 -> 768) + softplus(+dt_bias) ----------------
__global__ void __launch_bounds__(256) dt_proj() {
    const int o0 = threadIdx.x * 3;
    float wr[24][3];
    #pragma unroll
    for (int r = 0; r < 24; r++) {
        wr[r][0] = g_WdtT[r*768 + o0];
        wr[r][1] = g_WdtT[r*768 + o0 + 1];
        wr[r][2] = g_WdtT[r*768 + o0 + 2];
    }
    const float b0 = g_bsum[o0], b1 = g_bsum[o0+1], b2 = g_bsum[o0+2];
    __shared__ float sin[64*24];
    const int row0 = blockIdx.x * 64;
    for (int e = threadIdx.x; e < 64*24; e += 256)
        sin[e] = g_dts24[row0*24 + e];
    __syncthreads();
    for (int rr = 0; rr < 64; rr++) {
        const float* s = sin + rr*24;
        float a0 = b0, a1 = b1, a2 = b2;
        #pragma unroll
        for (int r = 0; r < 24; r++) {
            float sv = s[r];
            a0 = fmaf(sv, wr[r][0], a0);
            a1 = fmaf(sv, wr[r][1], a1);
            a2 = fmaf(sv, wr[r][2], a2);
        }
        float* o = g_dtsp + (size_t)(row0 + rr)*768 + o0;
        o[0] = fmaxf(a0, 0.f) + log1pf(__expf(-fabsf(a0)));
        o[1] = fmaxf(a1, 0.f) + log1pf(__expf(-fabsf(a1)));
        o[2] = fmaxf(a2, 0.f) + log1pf(__expf(-fabsf(a2)));
    }
}

// ---------------- K5a: per-chunk scan aggregates ----------------
__global__ void __launch_bounds__(192) scan_pass1() {
    const int blk = blockIdx.x;
    const int c = blk & 63, k = (blk >> 6) & 3, b = blk >> 8;
    const int d = threadIdx.x;
    __shared__ float sBC[64][32];
    const float* bcbase = g_bc + ((b*4 + k)*4096 + c*64)*32;
    for (int e = d; e < 2048; e += 192) sBC[e>>5][e&31] = bcbase[e];
    __syncthreads();
    float Ae[16];
    const float* aep = g_Ae + (k*192 + d)*16;
    #pragma unroll
    for (int n = 0; n < 16; n++) Ae[n] = aep[n];
    float h[16], Ag[16];
    #pragma unroll
    for (int n = 0; n < 16; n++) { h[n] = 0.f; Ag[n] = 1.f; }
    const float* dtp  = g_dtsp + (b*4096 + c*64)*768 + k*192 + d;
    const float* ubuf = ((k & 1) ? g_xct : g_xcr) + b*4096*192 + d;
    for (int li = 0; li < 64; li++) {
        int l = c*64 + li;
        float dts = dtp[li*768];
        int pos = (k & 2) ? (4095 - l) : l;
        float du = dts * ubuf[pos*192];
        #pragma unroll
        for (int n = 0; n < 16; n++) {
            float a = __expf(dts * Ae[n]);
            Ag[n] *= a;
            h[n] = fmaf(a, h[n], du * sBC[li][n]);
        }
    }
    float2* outp = g_agg + (((b*4 + k)*64 + c)*192 + d)*16;
    #pragma unroll
    for (int n = 0; n < 16; n++) outp[n] = make_float2(Ag[n], h[n]);
}

// ---------------- K5b: scan across chunk aggregates ----------------
__global__ void scan_pass2() {
    int t = blockIdx.x*blockDim.x + threadIdx.x;
    if (t >= 8*3072) return;
    int bk = t / 3072, dn = t % 3072;
    const float2* ag = g_agg + bk*64*3072 + dn;
    float* hs = g_hst + bk*64*3072 + dn;
    float h = 0.f;
    #pragma unroll 8
    for (int c = 0; c < 64; c++) {
        hs[c*3072] = h;
        float2 ab = ag[c*3072];
        h = fmaf(ab.x, h, ab.y);
    }
}

// ---------------- K5c: replay chunks with correct start state, produce y ----------------
__global__ void __launch_bounds__(192) scan_pass3(const float* __restrict__ Dskip) {
    const int blk = blockIdx.x;
    const int c = blk & 63, k = (blk >> 6) & 3, b = blk >> 8;
    const int d = threadIdx.x;
    __shared__ float sBC[64][32];
    const float* bcbase = g_bc + ((b*4 + k)*4096 + c*64)*32;
    for (int e = d; e < 2048; e += 192) sBC[e>>5][e&31] = bcbase[e];
    __syncthreads();
    float Ae[16];
    const float* aep = g_Ae + (k*192 + d)*16;
    #pragma unroll
    for (int n = 0; n < 16; n++) Ae[n] = aep[n];
    float h[16];
    const float* hs = g_hst + ((b*4 + k)*64 + c)*3072 + d*16;
    #pragma unroll
    for (int n = 0; n < 16; n++) h[n] = hs[n];
    const float Dk = Dskip[k*192 + d];
    const float* dtp  = g_dtsp + (b*4096 + c*64)*768 + k*192 + d;
    const float* ubuf = ((k & 1) ? g_xct : g_xcr) + b*4096*192 + d;
    float* yout = g_ys + ((b*4 + k)*4096 + c*64)*192 + d;
    for (int li = 0; li < 64; li++) {
        int l = c*64 + li;
        float dts = dtp[li*768];
        int pos = (k & 2) ? (4095 - l) : l;
        float u = ubuf[pos*192];
        float du = dts * u;
        float y = 0.f;
        #pragma unroll
        for (int n = 0; n < 16; n++) {
            float a = __expf(dts * Ae[n]);
            h[n] = fmaf(a, h[n], du * sBC[li][n]);
            y = fmaf(h[n], sBC[li][16 + n], y);
        }
        yout[li*192] = fmaf(u, Dk, y);
    }
}

// ---------------- K6: cross-merge + LayerNorm + z-gate (one warp per pixel) ----------------
__global__ void __launch_bounds__(256) merge_ln(const float* __restrict__ gamma,
                                                const float* __restrict__ beta) {
    const int warp = threadIdx.x >> 5, lane = threadIdx.x & 31;
    const int pix = blockIdx.x*8 + warp;
    const int b = pix >> 12, pl = pix & 4095;
    const int l1 = ((pl & 63) << 6) | (pl >> 6);
    const int l2 = 4095 - pl;
    const int l3 = 4095 - l1;
    const float* y0 = g_ys + ((b*4 + 0)*4096 + pl)*192;
    const float* y1 = g_ys + ((b*4 + 1)*4096 + l1)*192;
    const float* y2 = g_ys + ((b*4 + 2)*4096 + l2)*192;
    const float* y3 = g_ys + ((b*4 + 3)*4096 + l3)*192;
    float y[6]; float s = 0.f;
    #pragma unroll
    for (int i = 0; i < 6; i++) {
        int dd = lane + 32*i;
        y[i] = y0[dd] + y1[dd] + y2[dd] + y3[dd];
        s += y[i];
    }
    #pragma unroll
    for (int o = 16; o; o >>= 1) s += __shfl_xor_sync(0xffffffffu, s, o);
    float mu = s * (1.f/192.f);
    float v = 0.f;
    #pragma unroll
    for (int i = 0; i < 6; i++) { float t = y[i] - mu; v = fmaf(t, t, v); }
    #pragma unroll
    for (int o = 16; o; o >>= 1) v += __shfl_xor_sync(0xffffffffu, v, o);
    float rstd = rsqrtf(v * (1.f/192.f) + 1e-5f);
    const float* zr = g_z + (size_t)pix*192;
    float* yo = g_yn + (size_t)pix*192;
    #pragma unroll
    for (int i = 0; i < 6; i++) {
        int dd = lane + 32*i;
        float t = fmaf((y[i] - mu)*rstd, gamma[dd], beta[dd]);
        yo[dd] = t * zr[dd];
    }
}

// ---------------- K7: out projection (8192x192 @ 192x96) ----------------
__global__ void __launch_bounds__(256) k7_gemm(const float* __restrict__ b_out,
                                               float* __restrict__ out) {
    __shared__ float As[64][17];
    __shared__ float Bs[16][96];
    const int tid = threadIdx.x;
    const int tx = tid & 15, ty = tid >> 4;
    const int m0 = blockIdx.x * 64;
    const int lm = tid >> 2, lq = tid & 3;
    float acc[4][6] = {};
    for (int k0 = 0; k0 < 192; k0 += 16) {
        float4 av = *(const float4*)(g_yn + (m0 + lm)*192 + k0 + lq*4);
        As[lm][lq*4+0] = av.x; As[lm][lq*4+1] = av.y;
        As[lm][lq*4+2] = av.z; As[lm][lq*4+3] = av.w;
        #pragma unroll
        for (int q = 0; q < 6; q++) {
            int e = tid + q*256;
            Bs[e/96][e%96] = g_WoutT[(k0 + e/96)*96 + (e%96)];
        }
        __syncthreads();
        #pragma unroll
        for (int kk = 0; kk < 16; kk++) {
            float ar[4], br[6];
            #pragma unroll
            for (int i = 0; i < 4; i++) ar[i] = As[ty + 16*i][kk];
            #pragma unroll
            for (int j = 0; j < 6; j++) br[j] = Bs[kk][tx + 16*j];
            #pragma unroll
            for (int i = 0; i < 4; i++)
                #pragma unroll
                for (int j = 0; j < 6; j++) acc[i][j] = fmaf(ar[i], br[j], acc[i][j]);
        }
        __syncthreads();
    }
    #pragma unroll
    for (int i = 0; i < 4; i++) {
        int m = m0 + ty + 16*i;
        #pragma unroll
        for (int j = 0; j < 6; j++) {
            int col = tx + 16*j;
            out[m*96 + col] = acc[i][j] + b_out[col];
        }
    }
}

// ---------------- launch ----------------
extern "C" void kernel_launch(void* const* d_in, const int* in_sizes, int n_in,
                              void* d_out, int out_size) {
    const float* x       = (const float*)d_in[0];
    const float* W_in    = (const float*)d_in[1];
    const float* b_in    = (const float*)d_in[2];
    const float* conv_w  = (const float*)d_in[3];
    const float* conv_b  = (const float*)d_in[4];
    const float* W_xp    = (const float*)d_in[5];
    const float* b_xp    = (const float*)d_in[6];
    const float* W_dt    = (const float*)d_in[7];
    const float* b_dt    = (const float*)d_in[8];
    const float* A_log   = (const float*)d_in[9];
    const float* D_skip  = (const float*)d_in[10];
    const float* dt_bias = (const float*)d_in[11];
    const float* W_out   = (const float*)d_in[12];
    const float* b_out   = (const float*)d_in[13];
    const float* gamma   = (const float*)d_in[14];
    const float* beta    = (const float*)d_in[15];
    float* out = (float*)d_out;

    prep_kernel<<<256, 256>>>(W_in, W_xp, W_dt, W_out, A_log, b_dt, dt_bias);
    k1_gemm<<<dim3(MROWS/64, 6), 128>>>(x, b_in);
    conv_dw<<<NB*64, 256>>>(conv_w, conv_b);
    k3_gemm<<<dim3(MROWS/64, 3, 4), 128>>>();
    k3_reduce<<<(MROWS*KP + 255)/256, 256>>>(b_xp);
    dt_proj<<<MROWS/64, 256>>>();
    scan_pass1<<<NB*KDIR*NCH, 192>>>();
    scan_pass2<<<96, 256>>>();
    scan_pass3<<<NB*KDIR*NCH, 192>>>(D_skip);
    merge_ln<<<MROWS/8, 256>>>(gamma, beta);
    k7_gemm<<<dim3(MROWS/64, 1), 256>>>(b_out, out);
}